// round 9
// baseline (speedup 1.0000x reference)
#include <cuda_runtime.h>
#include <cuda_bf16.h>
#include <mma.h>
#include <math.h>

using namespace nvcuda;

#define NTOK 8192
#define CDIM 256
#define NHEAD 4
#define QKVN 768
#define MAXDIST 4.242640687119285f  /* sqrt(18) */

// ---------------- scratch ----------------
__device__ float g_qkv[NTOK * QKVN];      // silu(x@W_qkv)  (q|k|v)
__device__ float g_q[NTOK * CDIM];
__device__ float g_k[NTOK * CDIM];
__device__ float g_att[NTOK * CDIM];
__device__ float g_merged[NTOK * CDIM];
__device__ float g_width[NTOK * NHEAD];
__device__ float g_sharp[NTOK * NHEAD];
__device__ float g_rmsinv[NTOK];
__device__ float g_wpT[8 * 256];          // W_wp transposed [o][c]

__device__ __forceinline__ float sigmoidf_(float x) { return 1.f / (1.f + __expf(-x)); }
__device__ __forceinline__ float siluf_(float x) { return x * sigmoidf_(x); }

__device__ __forceinline__ void split_bf16(float f, __nv_bfloat16& hi, __nv_bfloat16& lo) {
    hi = __float2bfloat16(f);
    lo = __float2bfloat16(f - __bfloat162float(hi));
}

// ---------------- tensor-core GEMM: 128x64 block tile, split-bf16 (3 HMMA) ----------------
#define A_LD 40
#define B_LD 72
#define C_LD 36

template <int EPI>
__global__ void __launch_bounds__(256) gemm_mma(
    const float* __restrict__ A, int lda,
    const float* __restrict__ B, int ldb,
    float* __restrict__ Cmat, int ldc,
    const float* __restrict__ bias,
    const float* __restrict__ wonorm)
{
    __shared__ __align__(16) unsigned char smraw[36992];
    __nv_bfloat16 (*As)[128][A_LD] = (__nv_bfloat16(*)[128][A_LD])smraw;
    __nv_bfloat16 (*Bs)[32][B_LD]  = (__nv_bfloat16(*)[32][B_LD])(smraw + 2 * 128 * A_LD * 2);
    float (*Cs)[32][C_LD]          = (float(*)[32][C_LD])smraw;

    int tid = threadIdx.x;
    int warp = tid >> 5, lane = tid & 31;
    int wm = warp >> 1, wn = warp & 1;
    int rowBase = blockIdx.y * 128;
    int colBase = blockIdx.x * 64;

    wmma::fragment<wmma::accumulator, 16, 16, 16, float> cf[2][2];
#pragma unroll
    for (int i = 0; i < 2; i++)
#pragma unroll
        for (int j = 0; j < 2; j++) wmma::fill_fragment(cf[i][j], 0.f);

    int ar = tid >> 3, ac4 = (tid & 7) * 4;

    for (int kt = 0; kt < 256; kt += 32) {
        float4 av[4], bv[2];
#pragma unroll
        for (int p = 0; p < 4; p++)
            av[p] = *(const float4*)(A + (size_t)(rowBase + ar + p * 32) * lda + kt + ac4);
#pragma unroll
        for (int p = 0; p < 2; p++) {
            int idx = tid + p * 256;
            bv[p] = *(const float4*)(B + (size_t)(kt + (idx >> 4)) * ldb + colBase + (idx & 15) * 4);
        }
        __syncthreads();
#pragma unroll
        for (int p = 0; p < 4; p++) {
            int r = ar + p * 32;
            float e[4] = {av[p].x, av[p].y, av[p].z, av[p].w};
#pragma unroll
            for (int q = 0; q < 4; q++) {
                __nv_bfloat16 hi, lo;
                split_bf16(e[q], hi, lo);
                As[0][r][ac4 + q] = hi;
                As[1][r][ac4 + q] = lo;
            }
        }
#pragma unroll
        for (int p = 0; p < 2; p++) {
            int idx = tid + p * 256;
            int r = idx >> 4, c4 = (idx & 15) * 4;
            float e[4] = {bv[p].x, bv[p].y, bv[p].z, bv[p].w};
#pragma unroll
            for (int q = 0; q < 4; q++) {
                __nv_bfloat16 hi, lo;
                split_bf16(e[q], hi, lo);
                Bs[0][r][c4 + q] = hi;
                Bs[1][r][c4 + q] = lo;
            }
        }
        __syncthreads();

#pragma unroll
        for (int ks = 0; ks < 32; ks += 16) {
            wmma::fragment<wmma::matrix_a, 16, 16, 16, __nv_bfloat16, wmma::row_major> ah[2], al[2];
            wmma::fragment<wmma::matrix_b, 16, 16, 16, __nv_bfloat16, wmma::row_major> bh[2], bl[2];
#pragma unroll
            for (int i = 0; i < 2; i++) {
                wmma::load_matrix_sync(ah[i], &As[0][wm * 32 + i * 16][ks], A_LD);
                wmma::load_matrix_sync(al[i], &As[1][wm * 32 + i * 16][ks], A_LD);
            }
#pragma unroll
            for (int j = 0; j < 2; j++) {
                wmma::load_matrix_sync(bh[j], &Bs[0][ks][wn * 32 + j * 16], B_LD);
                wmma::load_matrix_sync(bl[j], &Bs[1][ks][wn * 32 + j * 16], B_LD);
            }
#pragma unroll
            for (int i = 0; i < 2; i++)
#pragma unroll
                for (int j = 0; j < 2; j++) {
                    wmma::mma_sync(cf[i][j], ah[i], bh[j], cf[i][j]);
                    wmma::mma_sync(cf[i][j], ah[i], bl[j], cf[i][j]);
                    wmma::mma_sync(cf[i][j], al[i], bh[j], cf[i][j]);
                }
        }
    }

    __syncthreads();
#pragma unroll
    for (int i = 0; i < 2; i++)
#pragma unroll
        for (int j = 0; j < 2; j++)
            wmma::store_matrix_sync(&Cs[warp][i * 16][j * 16], cf[i][j], C_LD, wmma::mem_row_major);
    __syncwarp();

#pragma unroll 4
    for (int rr = 0; rr < 32; rr++) {
        int r = rowBase + wm * 32 + rr;
        int c = colBase + wn * 32 + lane;
        float val = Cs[warp][rr][lane];
        if (EPI == 0) {
            Cmat[(size_t)r * ldc + c] = siluf_(val);
        } else {
            float t = val + bias[c];
            float g = sigmoidf_(siluf_(t));
            float vv = A[(size_t)r * lda + c];
            float att = g_att[(size_t)r * CDIM + c] * g_rmsinv[r] * wonorm[c];
            Cmat[(size_t)r * ldc + c] = g * vv + (1.f - g) * att;
        }
    }
}

// ---------------- transpose W_wp -> [8][256] ----------------
__global__ void transpose_wp(const float* __restrict__ Wwp)
{
    int c = threadIdx.x;
#pragma unroll
    for (int o = 0; o < 8; o++)
        g_wpT[o * 256 + c] = Wwp[c * 8 + o];
}

// ---------------- fused rmsnorm + RoPE (pos = head index!) + width/sharp ----------------
__global__ void __launch_bounds__(256) norm_rope_wp(
    const float* __restrict__ x,
    const float* __restrict__ bwp,
    const float* __restrict__ wqn, const float* __restrict__ wkn)
{
    int lane = threadIdx.x & 31;
    int tok = blockIdx.x * 8 + (threadIdx.x >> 5);
    const float4* row = (const float4*)(g_qkv + (size_t)tok * QKVN);

    float qv[8], kv[8];
    {
        float4 q0 = row[lane * 2], q1 = row[lane * 2 + 1];
        float4 k0 = row[64 + lane * 2], k1 = row[64 + lane * 2 + 1];
        qv[0] = q0.x; qv[1] = q0.y; qv[2] = q0.z; qv[3] = q0.w;
        qv[4] = q1.x; qv[5] = q1.y; qv[6] = q1.z; qv[7] = q1.w;
        kv[0] = k0.x; kv[1] = k0.y; kv[2] = k0.z; kv[3] = k0.w;
        kv[4] = k1.x; kv[5] = k1.y; kv[6] = k1.z; kv[7] = k1.w;
    }
    float sq = 0.f, sk = 0.f;
#pragma unroll
    for (int e = 0; e < 8; e++) { sq += qv[e] * qv[e]; sk += kv[e] * kv[e]; }
#pragma unroll
    for (int off = 1; off < 8; off <<= 1) {
        sq += __shfl_xor_sync(0xffffffffu, sq, off);
        sk += __shfl_xor_sync(0xffffffffu, sk, off);
    }
    float rq = rsqrtf(sq * (1.f / 64.f) + 1e-6f);
    float rk = rsqrtf(sk * (1.f / 64.f) + 1e-6f);

    int h = lane >> 3;
    int dl = lane & 7;
#pragma unroll
    for (int e = 0; e < 8; e++) {
        int d = dl * 8 + e;
        qv[e] *= rq * wqn[d];
        kv[e] *= rk * wkn[d];
    }
    float sgn = (lane & 4) ? 1.f : -1.f;
#pragma unroll
    for (int e = 0; e < 8; e++) {
        float qp = __shfl_xor_sync(0xffffffffu, qv[e], 4);
        float kp = __shfl_xor_sync(0xffffffffu, kv[e], 4);
        int f = (lane & 3) * 8 + e;
        float freq = exp2f(-(float)f * (13.287712379549449f / 32.f));
        float ang = (float)h * freq;
        float ss, cc;
        __sincosf(ang, &ss, &cc);
        qv[e] = qv[e] * cc + sgn * qp * ss;
        kv[e] = kv[e] * cc + sgn * kp * ss;
    }
    {
        float4* qo = (float4*)(g_q + (size_t)tok * CDIM);
        float4* ko = (float4*)(g_k + (size_t)tok * CDIM);
        qo[lane * 2]     = make_float4(qv[0], qv[1], qv[2], qv[3]);
        qo[lane * 2 + 1] = make_float4(qv[4], qv[5], qv[6], qv[7]);
        ko[lane * 2]     = make_float4(kv[0], kv[1], kv[2], kv[3]);
        ko[lane * 2 + 1] = make_float4(kv[4], kv[5], kv[6], kv[7]);
    }

    const float4* xr4 = (const float4*)(x + (size_t)tok * CDIM);
    float4 x0 = xr4[lane * 2], x1 = xr4[lane * 2 + 1];
    float keep = 0.f;
#pragma unroll
    for (int o = 0; o < 8; o++) {
        const float4* wr = (const float4*)(g_wpT + o * 256);
        float4 w0 = wr[lane * 2], w1 = wr[lane * 2 + 1];
        float p = x0.x * w0.x + x0.y * w0.y + x0.z * w0.z + x0.w * w0.w
                + x1.x * w1.x + x1.y * w1.y + x1.z * w1.z + x1.w * w1.w;
#pragma unroll
        for (int off = 16; off >= 1; off >>= 1) p += __shfl_xor_sync(0xffffffffu, p, off);
        if (lane == o) keep = p;
    }
    if (lane < 8) {
        float w = siluf_(keep + bwp[lane]);
        if (lane < 4) g_width[tok * 4 + lane] = sigmoidf_(w) * MAXDIST + 0.5f;
        else          g_sharp[tok * 4 + lane - 4] = sigmoidf_(w) * 9.5f + 0.5f;
    }
}

// ---------------- local window attention (swizzled stride-64 k/v, q via L1) ----------------
// smem = 2 * 196 * 64 floats = 98KB -> 2 CTAs/SM.
// swizzle: float4-group g of row r stored at group (g ^ (r & 15)).
__global__ void __launch_bounds__(256) attn_kernel()
{
    extern __shared__ float sm[];
    float* k_s = sm;                  // 196 * 64, swizzled
    float* v_s = sm + 196 * 64;       // 196 * 64, swizzled

    int tile = blockIdx.x;
    int b = blockIdx.y;
    int h = blockIdx.z;
    int ty0 = (tile >> 3) * 8, tx0 = (tile & 7) * 8;
    int tid = threadIdx.x;

    // halo fill: 196 rows x 16 float4-groups
    for (int idx = tid; idx < 196 * 16; idx += 256) {
        int r = idx >> 4;
        int g = idx & 15;
        int hy = ty0 + (r / 14) - 3;
        int hx = tx0 + (r % 14) - 3;
        float4 kq = make_float4(0.f, 0.f, 0.f, 0.f);
        float4 vq = make_float4(0.f, 0.f, 0.f, 0.f);
        if (hy >= 0 && hy < 64 && hx >= 0 && hx < 64) {
            int tokg = b * 4096 + hy * 64 + hx;
            kq = *(const float4*)&g_k[(size_t)tokg * CDIM + h * 64 + g * 4];
            vq = *(const float4*)&g_qkv[(size_t)tokg * QKVN + 512 + h * 64 + g * 4];
        }
        int sg = g ^ (r & 15);
        *(float4*)&k_s[r * 64 + sg * 4] = kq;
        *(float4*)&v_s[r * 64 + sg * 4] = vq;
    }
    __syncthreads();

    int warpId = tid >> 5, lane = tid & 31;
    int w1 = lane, w2 = lane + 32;
    bool has2 = (w2 < 49);
    int off1 = (w1 / 7) * 14 + (w1 % 7);
    int off2 = has2 ? (w2 / 7) * 14 + (w2 % 7) : 0;
    float di1 = (float)(w1 / 7 - 3), dj1 = (float)(w1 % 7 - 3);
    float rd1 = sqrtf(di1 * di1 + dj1 * dj1);
    float di2 = (float)(w2 / 7 - 3), dj2 = (float)(w2 % 7 - 3);
    float rd2 = sqrtf(di2 * di2 + dj2 * dj2);

    int gl = lane >> 2, el = lane & 3;      // v-pass lane->(group,elem) for o1
    int gh = gl + 8;                        // for o2 (d = lane+32)

    for (int t = 0; t < 8; t++) {
        int ly = warpId, lx = t;
        int base = ly * 14 + lx;
        int tokg = b * 4096 + (ty0 + ly) * 64 + (tx0 + lx);
        const float4* qg = (const float4*)&g_q[(size_t)tokg * CDIM + h * 64];

        int r1 = base + off1, r2 = base + off2;
        const float* k1row = &k_s[r1 * 64];
        const float* k2row = &k_s[r2 * 64];
        int m1x = r1 & 15, m2x = r2 & 15;

        float4 a1 = make_float4(0.f, 0.f, 0.f, 0.f);
        float4 a2 = make_float4(0.f, 0.f, 0.f, 0.f);
#pragma unroll
        for (int g = 0; g < 16; g++) {
            float4 q4 = __ldg(qg + g);
            float4 ka = *(const float4*)&k1row[(g ^ m1x) << 2];
            float4 kb = *(const float4*)&k2row[(g ^ m2x) << 2];
            a1.x += q4.x * ka.x; a1.y += q4.y * ka.y;
            a1.z += q4.z * ka.z; a1.w += q4.w * ka.w;
            a2.x += q4.x * kb.x; a2.y += q4.y * kb.y;
            a2.z += q4.z * kb.z; a2.w += q4.w * kb.w;
        }
        float s1 = (a1.x + a1.y) + (a1.z + a1.w);
        float s2 = (a2.x + a2.y) + (a2.z + a2.w);

        float width = g_width[tokg * NHEAD + h];
        float sharp = g_sharp[tokg * NHEAD + h];
        float m1 = s1 * 0.125f - (1.f - sigmoidf_((width - rd1) * sharp)) * 10000.f;
        float m2 = has2
                   ? s2 * 0.125f - (1.f - sigmoidf_((width - rd2) * sharp)) * 10000.f
                   : -1e30f;
        float mx = fmaxf(m1, m2);
#pragma unroll
        for (int off = 16; off >= 1; off >>= 1)
            mx = fmaxf(mx, __shfl_xor_sync(0xffffffffu, mx, off));
        float e1 = __expf(m1 - mx);
        float e2 = has2 ? __expf(m2 - mx) : 0.f;
        float ssum = e1 + e2;
#pragma unroll
        for (int off = 16; off >= 1; off >>= 1)
            ssum += __shfl_xor_sync(0xffffffffu, ssum, off);
        float inv = 1.f / ssum;
        float aw1 = e1 * inv, aw2 = e2 * inv;

        float o1 = 0.f, o2 = 0.f;
#pragma unroll
        for (int w = 0; w < 49; w++) {
            float a = (w < 32) ? __shfl_sync(0xffffffffu, aw1, w)
                               : __shfl_sync(0xffffffffu, aw2, w - 32);
            int vrow = base + (w / 7) * 14 + (w % 7);
            int vm = vrow & 15;
            o1 += a * v_s[vrow * 64 + ((gl ^ vm) << 2) + el];
            o2 += a * v_s[vrow * 64 + ((gh ^ vm) << 2) + el];
        }
        g_att[(size_t)tokg * CDIM + h * 64 + lane] = o1;
        g_att[(size_t)tokg * CDIM + h * 64 + lane + 32] = o2;
    }
}

// ---------------- per-token inverse rms of attention output ----------------
__global__ void __launch_bounds__(256) rmsinv_kernel()
{
    int lane = threadIdx.x & 31;
    int tok = blockIdx.x * 8 + (threadIdx.x >> 5);
    const float4* row = (const float4*)(g_att + (size_t)tok * CDIM);
    float s = 0.f;
#pragma unroll
    for (int i = 0; i < 2; i++) {
        float4 v = row[lane + i * 32];
        s += v.x * v.x + v.y * v.y + v.z * v.z + v.w * v.w;
    }
#pragma unroll
    for (int off = 16; off >= 1; off >>= 1) s += __shfl_xor_sync(0xffffffffu, s, off);
    if (lane == 0) g_rmsinv[tok] = rsqrtf(s * (1.f / 256.f) + 1e-6f);
}

// ---------------- launch ----------------
extern "C" void kernel_launch(void* const* d_in, const int* in_sizes, int n_in,
                              void* d_out, int out_size)
{
    const float* x       = (const float*)d_in[0];
    const float* W_qkv   = (const float*)d_in[1];
    const float* w_qnorm = (const float*)d_in[2];
    const float* w_knorm = (const float*)d_in[3];
    const float* W_wp    = (const float*)d_in[4];
    const float* b_wp    = (const float*)d_in[5];
    const float* w_onorm = (const float*)d_in[6];
    const float* W_out   = (const float*)d_in[7];
    const float* W_gate  = (const float*)d_in[8];
    const float* b_gate  = (const float*)d_in[9];
    float* out = (float*)d_out;

    float *p_qkv, *p_merged;
    cudaGetSymbolAddress((void**)&p_qkv, g_qkv);
    cudaGetSymbolAddress((void**)&p_merged, g_merged);

    // 0) transpose W_wp
    transpose_wp<<<1, 256>>>(W_wp);

    // 1) qkv = silu(x @ W_qkv)
    gemm_mma<0><<<dim3(12, 64), 256>>>(x, 256, W_qkv, 768, p_qkv, 768, nullptr, nullptr);

    // 2) rmsnorm + rope (q,k) + width/sharp projection
    norm_rope_wp<<<1024, 256>>>(x, b_wp, w_qnorm, w_knorm);

    // 3) local attention
    size_t smem = (size_t)(196 * 64 * 2) * sizeof(float);
    cudaFuncSetAttribute(attn_kernel, cudaFuncAttributeMaxDynamicSharedMemorySize, (int)smem);
    attn_kernel<<<dim3(64, 2, 4), 256, smem>>>();

    // 4) per-token rms of attention output
    rmsinv_kernel<<<1024, 256>>>();

    // 5) gate GEMM + fused rmsnorm-scale + gate-merge
    gemm_mma<1><<<dim3(4, 64), 256>>>(p_qkv + 512, 768, W_gate, 256, p_merged, 256,
                                      b_gate, w_onorm);

    // 6) out = silu(merged @ W_out)
    gemm_mma<0><<<dim3(4, 64), 256>>>(p_merged, 256, W_out, 256, out, 256,
                                      nullptr, nullptr);
}